// round 3
// baseline (speedup 1.0000x reference)
#include <cuda_runtime.h>
#include <stdint.h>

// FullMultiEmbedding: out[b, e, :] = weight[e, :] * psw[i] for each flat index i
// in bag b (e = input_[i]); zero elsewhere. Output [B, NUM_EMB, D] fp32.
//
// Inputs (metadata order) — NOTE: JAX default x64-disabled, so "int64" arrays
// are actually int32 on the wire:
//   d_in[0] input_             int32  [L]        (L = 12800)
//   d_in[1] offsets            int32  [B]        (B = 256)
//   d_in[2] per_sample_weights float32 [L]
//   d_in[3] weight             float32 [NUM_EMB, D]  (10000 x 64)
// Output: float32, out_size = B * NUM_EMB * D = 163,840,000

static constexpr int D = 64;           // embedding dim (16 float4 per row)
static constexpr int D4 = D / 4;       // 16

// ---------------------------------------------------------------------------
// Kernel 1: zero the full output with 16B vector stores (HBM-write bound).
// ---------------------------------------------------------------------------
__global__ void zero_kernel(float4* __restrict__ out, long long n4) {
    long long i = (long long)blockIdx.x * blockDim.x + threadIdx.x;
    long long stride = (long long)gridDim.x * blockDim.x;
    const float4 z = make_float4(0.f, 0.f, 0.f, 0.f);
    #pragma unroll 4
    for (; i < n4; i += stride) {
        out[i] = z;
    }
}

// ---------------------------------------------------------------------------
// Kernel 2: scatter weighted embedding rows.
// 16 threads per flat index: thread t handles float4 #(t&15) of the row.
// Bag id resolved by binary search over offsets (B entries, L2-resident).
// ---------------------------------------------------------------------------
__global__ void scatter_kernel(const int* __restrict__ input_,
                               const int* __restrict__ offsets,
                               const float* __restrict__ psw,
                               const float4* __restrict__ weight,
                               float4* __restrict__ out,
                               int L, int B, int num_emb) {
    int t = blockIdx.x * blockDim.x + threadIdx.x;
    int i  = t >> 4;     // flat index id
    int d4 = t & 15;     // float4 column within the 64-float row
    if (i >= L) return;

    // binary search: largest b with offsets[b] <= i
    int lo = 0, hi = B - 1;
    while (lo < hi) {
        int mid = (lo + hi + 1) >> 1;
        if (offsets[mid] <= i) lo = mid; else hi = mid - 1;
    }

    int e = input_[i];
    // defensive clamp (garbage index would corrupt memory)
    if (e < 0 || e >= num_emb) return;

    float w = psw[i];
    float4 v = weight[(long long)e * D4 + d4];
    v.x *= w; v.y *= w; v.z *= w; v.w *= w;

    long long dst = ((long long)lo * num_emb + e) * D4 + d4;
    out[dst] = v;
}

// ---------------------------------------------------------------------------
extern "C" void kernel_launch(void* const* d_in, const int* in_sizes, int n_in,
                              void* d_out, int out_size) {
    const int*   input_  = (const int*)d_in[0];
    const int*   offsets = (const int*)d_in[1];
    const float* psw     = (const float*)d_in[2];
    const float* weight  = (const float*)d_in[3];
    float* out = (float*)d_out;

    const int L = in_sizes[0];
    const int B = in_sizes[1];
    const int weight_elems = in_sizes[3];
    const int num_emb = weight_elems / D;

    // --- zero pass: full-output 16B stores ---
    long long n4 = (long long)out_size / 4;
    int zthreads = 256;
    int zblocks = 148 * 32;   // grid-stride, ~1.2M threads
    zero_kernel<<<zblocks, zthreads>>>((float4*)out, n4);

    // --- scatter pass: 16 threads per flat index ---
    int sthreads = 256;
    int total = L * 16;
    int sblocks = (total + sthreads - 1) / sthreads;
    scatter_kernel<<<sblocks, sthreads>>>(input_, offsets, psw,
                                          (const float4*)weight,
                                          (float4*)out, L, B, num_emb);
}